// round 15
// baseline (speedup 1.0000x reference)
#include <cuda_runtime.h>

// ---------------------------------------------------------------------------
// GraphSAGE 2-layer: N=100000 nodes, E=1.6M edges, 128 -> 128(relu) -> 64
// Aggregation AFTER the linear map (linearity of mean):
//   mean(h[src]) @ W_l == mean((h@W_l)[src]).
//
// CSR build is a deterministic, atomic-free sort (atomics fault with 717 on
// this setup; edge_index is int32). R14: 724us with 21 two-way merge passes
// (~233us). This build: per-thread 8-element sorting network + 4-way merge
// passes (1 + 9 kernels), keys packed (dst<<17 | src) so extraction is a
// mask and per-node sources come out sorted (better gather locality).
// ---------------------------------------------------------------------------

#define MAXN 100000
#define MAXE 1600000
#define SRC_BITS 17
#define SRC_MASK ((1u << SRC_BITS) - 1u)
typedef unsigned long long u64;

__device__ float g_y[MAXN * 128];     // x @ W_l1
__device__ float g_agg1[MAXN * 128];  // gathered sum of g_y
__device__ float g_h[MAXN * 128];     // relu layer-1 output
__device__ float g_z[MAXN * 64];      // h @ W_l2
__device__ float g_agg2[MAXN * 64];   // gathered sum of g_z
__device__ float g_deg[MAXN];
__device__ u64 g_keyA[MAXE];
__device__ u64 g_keyB[MAXE];
__device__ int g_off[MAXN + 1];
__device__ int g_csr_src[MAXE];

// ---------------------------------------------------------------------------
// Load 8 consecutive edges, sort (dst<<17|src) keys in registers with a
// Batcher odd-even mergesort network (19 CEs, static indices), store runs
// of 8. Out-of-range slots sort to the end as ULLONG_MAX (not stored).
__global__ void sort8_kernel(const int* __restrict__ ei,
                             u64* __restrict__ key, int E) {
    int base = (blockIdx.x * blockDim.x + threadIdx.x) * 8;
    if (base >= E) return;
    u64 k[8];
#pragma unroll
    for (int t = 0; t < 8; t++) {
        int e = base + t;
        if (e < E) {
            u64 d = (u64)(unsigned int)ei[E + e];
            u64 s = (u64)(unsigned int)ei[e];
            k[t] = (d << SRC_BITS) | s;
        } else {
            k[t] = ~0ULL;
        }
    }
#define CE(i, j) { u64 lo = k[i] < k[j] ? k[i] : k[j]; \
                   u64 hi = k[i] < k[j] ? k[j] : k[i]; k[i] = lo; k[j] = hi; }
    CE(0,1) CE(2,3) CE(4,5) CE(6,7)
    CE(0,2) CE(1,3) CE(4,6) CE(5,7)
    CE(1,2) CE(5,6)
    CE(0,4) CE(1,5) CE(2,6) CE(3,7)
    CE(2,4) CE(3,5)
    CE(1,2) CE(3,4) CE(5,6)
#undef CE
#pragma unroll
    for (int t = 0; t < 8; t++)
        if (base + t < E) key[base + t] = k[t];
}

// 4-way merge pass: merge groups of 4 sorted runs of length W.
// Element in run r gets its output rank from: own offset + for each other
// run q, upper_bound (q<r) or lower_bound (q>r) — exact with duplicates.
__global__ void merge4_kernel(const u64* __restrict__ in,
                              u64* __restrict__ out, int E, int W) {
    int i = blockIdx.x * blockDim.x + threadIdx.x;
    if (i >= E) return;
    const int G = 4 * W;
    const int g0 = (i / G) * G;
    const int r = (i - g0) / W;
    const u64 k = in[i];
    int pos = g0 + (i - g0 - r * W);  // own offset within run
#pragma unroll
    for (int q = 0; q < 4; q++) {
        if (q == r) continue;
        int lo = g0 + q * W;
        int hi = lo + W;
        if (lo >= E) continue;
        if (hi > E) hi = E;
        const int b0 = lo;
        if (q < r) {  // upper_bound: first index with key > k
            while (lo < hi) { int mid = (lo + hi) >> 1;
                              if (in[mid] <= k) lo = mid + 1; else hi = mid; }
        } else {      // lower_bound: first index with key >= k
            while (lo < hi) { int mid = (lo + hi) >> 1;
                              if (in[mid] < k) lo = mid + 1; else hi = mid; }
        }
        pos += lo - b0;
    }
    out[pos] = k;
}

// off[n] = first position in sorted keys with dst >= n  (n in [0, M])
__global__ void bounds_kernel(const u64* __restrict__ keys,
                              int* __restrict__ off, int E, int M) {
    int n = blockIdx.x * blockDim.x + threadIdx.x;
    if (n > M) return;
    u64 target = ((u64)n) << SRC_BITS;
    int lo = 0, hi = E;
    while (lo < hi) {
        int mid = (lo + hi) >> 1;
        if (keys[mid] < target) lo = mid + 1; else hi = mid;
    }
    off[n] = lo;
}

__global__ void deg_kernel(const int* __restrict__ off,
                           float* __restrict__ degf, int M) {
    int n = blockIdx.x * blockDim.x + threadIdx.x;
    if (n < M) degf[n] = (float)(off[n + 1] - off[n]);
}

// csr_src[j] = low 17 bits of sorted key j (coalesced, no gather)
__global__ void extract_kernel(const u64* __restrict__ keys,
                               int* __restrict__ csr_src, int E) {
    int j = blockIdx.x * blockDim.x + threadIdx.x;
    if (j < E) csr_src[j] = (int)(keys[j] & SRC_MASK);
}

// Warp-cooperative gather: LPN = CH/4 lanes cover one node (float4 per lane).
// CH=128 -> 1 node/warp; CH=64 -> 2 nodes/warp. csr_src load is uniform
// within the lane group (broadcast); feature loads are LDG.128 coalesced.
// Sources are sorted per node -> good L2 locality. Deterministic order.
template <int CH>
__global__ void gather_kernel(const float* __restrict__ feat,
                              const int* __restrict__ csr_src,
                              const int* __restrict__ off,
                              float* __restrict__ agg, int M) {
    constexpr int LPN = CH / 4;    // lanes per node (32 or 16)
    constexpr int NPW = 32 / LPN;  // nodes per warp (1 or 2)
    const int gwarp = (blockIdx.x * blockDim.x + threadIdx.x) >> 5;
    const int lane = threadIdx.x & 31;
    const int n = gwarp * NPW + lane / LPN;
    if (n >= M) return;
    const int c = (lane % LPN) * 4;
    const int beg = off[n], end = off[n + 1];
    float4 acc = make_float4(0.f, 0.f, 0.f, 0.f);
#pragma unroll 4
    for (int j = beg; j < end; j++) {
        int s = csr_src[j];
        float4 v = *(const float4*)&feat[s * CH + c];
        acc.x += v.x; acc.y += v.y; acc.z += v.z; acc.w += v.w;
    }
    *(float4*)&agg[n * CH + c] = acc;
}

// ---------------------------------------------------------------------------
// Tiled SGEMM: C[M,BN] = A[M,128] @ W[128,BN]  (+ optional fused SAGE epilogue:
//   C = acc + agg[row]*inv_deg(row) + bias, optional relu)
// BM=128, BK=32, 256 threads, thread tile 8 x (BN/16).
// ---------------------------------------------------------------------------
template <int BN, bool EPI, bool RELU>
__global__ __launch_bounds__(256, 2)
void gemm128(const float* __restrict__ A, const float* __restrict__ W,
             const float* __restrict__ agg, const float* __restrict__ deg,
             const float* __restrict__ bias, float* __restrict__ C, int M) {
    constexpr int BM = 128, BK = 32, K = 128;
    constexpr int TM = 8;
    constexpr int TN = BN / 16;  // 8 (BN=128) or 4 (BN=64)

    __shared__ __align__(16) float As[BK][BM + 4];  // transposed A tile, padded
    __shared__ __align__(16) float Bs[BK][BN];

    const int tid = threadIdx.x;
    const int tx = tid % 16;  // column group
    const int ty = tid / 16;  // row group
    const int row0 = blockIdx.x * BM;

    float acc[TM][TN];
#pragma unroll
    for (int i = 0; i < TM; i++)
#pragma unroll
        for (int j = 0; j < TN; j++) acc[i][j] = 0.f;

    const int a_r = tid / 8;        // 0..31
    const int a_k = (tid % 8) * 4;  // 0..28

    constexpr int BTH = BN / 4;        // threads per k-row (32 or 16)
    constexpr int BKSTEP = 256 / BTH;  // 8 or 16
    const int b_k = tid / BTH;
    const int b_n = (tid % BTH) * 4;

    for (int k0 = 0; k0 < K; k0 += BK) {
#pragma unroll
        for (int it = 0; it < 4; it++) {
            int r = a_r + it * 32;
            int grow = row0 + r;
            float4 v = make_float4(0.f, 0.f, 0.f, 0.f);
            if (grow < M) v = *(const float4*)&A[grow * K + k0 + a_k];
            As[a_k + 0][r] = v.x;
            As[a_k + 1][r] = v.y;
            As[a_k + 2][r] = v.z;
            As[a_k + 3][r] = v.w;
        }
#pragma unroll
        for (int it = 0; it < BK / BKSTEP; it++) {
            int k = b_k + it * BKSTEP;
            *(float4*)&Bs[k][b_n] = *(const float4*)&W[(k0 + k) * BN + b_n];
        }
        __syncthreads();

#pragma unroll
        for (int kk = 0; kk < BK; kk++) {
            float a[TM];
#pragma unroll
            for (int i = 0; i < TM; i += 4) {
                float4 av = *(const float4*)&As[kk][ty * TM + i];
                a[i] = av.x; a[i + 1] = av.y; a[i + 2] = av.z; a[i + 3] = av.w;
            }
            float b[TN];
#pragma unroll
            for (int j = 0; j < TN; j += 4) {
                float4 bv = *(const float4*)&Bs[kk][tx * TN + j];
                b[j] = bv.x; b[j + 1] = bv.y; b[j + 2] = bv.z; b[j + 3] = bv.w;
            }
#pragma unroll
            for (int i = 0; i < TM; i++)
#pragma unroll
                for (int j = 0; j < TN; j++) acc[i][j] += a[i] * b[j];
        }
        __syncthreads();
    }

#pragma unroll
    for (int i = 0; i < TM; i++) {
        int row = row0 + ty * TM + i;
        if (row >= M) continue;
        float inv = 0.f;
        if (EPI) inv = 1.f / fmaxf(deg[row], 1.f);
#pragma unroll
        for (int j = 0; j < TN; j += 4) {
            int col = tx * TN + j;
            float4 o;
            float* po = (float*)&o;
#pragma unroll
            for (int q = 0; q < 4; q++) {
                float v = acc[i][j + q];
                if (EPI) v += agg[row * BN + col + q] * inv + bias[col + q];
                if (RELU) v = fmaxf(v, 0.f);
                po[q] = v;
            }
            *(float4*)&C[row * BN + col] = o;
        }
    }
}

// ---------------------------------------------------------------------------
extern "C" void kernel_launch(void* const* d_in, const int* in_sizes, int n_in,
                              void* d_out, int out_size) {
    const float* x       = (const float*)d_in[0];
    const int* ei        = (const int*)d_in[1];   // int32 (JAX x64 disabled)
    const float* Wl1     = (const float*)d_in[2];
    const float* Wr1     = (const float*)d_in[3];
    const float* b1      = (const float*)d_in[4];
    const float* Wl2     = (const float*)d_in[5];
    const float* Wr2     = (const float*)d_in[6];
    const float* b2      = (const float*)d_in[7];
    float* out           = (float*)d_out;

    const int M = in_sizes[0] / 128;  // n_nodes
    const int E = in_sizes[1] / 2;    // n_edges

    float *p_y, *p_agg1, *p_h, *p_z, *p_agg2, *p_deg;
    int *p_off, *p_csr;
    u64 *p_keyA, *p_keyB;
    cudaGetSymbolAddress((void**)&p_y,    g_y);
    cudaGetSymbolAddress((void**)&p_agg1, g_agg1);
    cudaGetSymbolAddress((void**)&p_h,    g_h);
    cudaGetSymbolAddress((void**)&p_z,    g_z);
    cudaGetSymbolAddress((void**)&p_agg2, g_agg2);
    cudaGetSymbolAddress((void**)&p_deg,  g_deg);
    cudaGetSymbolAddress((void**)&p_off,  g_off);
    cudaGetSymbolAddress((void**)&p_csr,  g_csr_src);
    cudaGetSymbolAddress((void**)&p_keyA, g_keyA);
    cudaGetSymbolAddress((void**)&p_keyB, g_keyB);

    const int eb = (E + 255) / 256;

    // ---- CSR build: 8-element register sort + 4-way merge passes ----
    {
        int threads = (E + 7) / 8;
        sort8_kernel<<<(threads + 255) / 256, 256>>>(ei, p_keyA, E);
    }
    u64* bufs[2] = {p_keyA, p_keyB};
    int cur = 0;
    for (int W = 8; W < E; W <<= 2) {
        merge4_kernel<<<eb, 256>>>(bufs[cur], bufs[cur ^ 1], E, W);
        cur ^= 1;
    }
    const u64* sorted = bufs[cur];
    bounds_kernel<<<(M + 256) / 256, 256>>>(sorted, p_off, E, M);
    deg_kernel<<<(M + 255) / 256, 256>>>(p_off, p_deg, M);
    extract_kernel<<<eb, 256>>>(sorted, p_csr, E);

    const int gemm_grid = (M + 127) / 128;

    // ---- Layer 1 ----
    gemm128<128, false, false><<<gemm_grid, 256>>>(x, Wl1, nullptr, nullptr,
                                                   nullptr, p_y, M);
    {
        int blocks = (M + 7) / 8;  // 1 node per warp, 8 warps per block
        gather_kernel<128><<<blocks, 256>>>(p_y, p_csr, p_off, p_agg1, M);
    }
    gemm128<128, true, true><<<gemm_grid, 256>>>(x, Wr1, p_agg1, p_deg, b1,
                                                 p_h, M);

    // ---- Layer 2 ----
    gemm128<64, false, false><<<gemm_grid, 256>>>(p_h, Wl2, nullptr, nullptr,
                                                  nullptr, p_z, M);
    {
        int blocks = (M + 15) / 16;  // 2 nodes per warp, 16 per block
        gather_kernel<64><<<blocks, 256>>>(p_z, p_csr, p_off, p_agg2, M);
    }
    gemm128<64, true, false><<<gemm_grid, 256>>>(p_h, Wr2, p_agg2, p_deg, b2,
                                                 out, M);
}